// round 3
// baseline (speedup 1.0000x reference)
#include <cuda_runtime.h>

// Problem constants
#define B_   2
#define T_   2048
#define D_   1024
#define H_   16
#define S_   16
#define HD_  64
#define BT_  (B_ * T_)     // 4096
#define N3D_ (3 * D_)      // 3072

// ---------------------------------------------------------------------------
// Workspaces (device globals — no allocation allowed)
// ---------------------------------------------------------------------------
__device__ float g_qkv[BT_ * N3D_];          // (b,t,{q,k,v},h,hd) = 50.3 MB
__device__ float g_attno[BT_ * D_];          // attention output (b,t,h,hd)
__device__ float g_qwa[B_ * H_ * T_ * S_];   // q splat weights * amplitude
__device__ float g_kw [B_ * H_ * T_ * S_];   // k splat weights
__device__ float g_centers[H_ * S_ * HD_];
__device__ float g_invvar[H_ * S_];
__device__ float g_amp[H_ * S_];
__device__ float g_shift[H_];                // per-head logit shift (softmax stability)
__device__ float g_invtemp;

typedef unsigned long long u64;

// ---------------------------------------------------------------------------
// Packed f32x2 helpers (FFMA2 — full-rate fp32 on Blackwell sm_100+)
// ---------------------------------------------------------------------------
__device__ __forceinline__ u64 pack2(float lo, float hi) {
    u64 r;
    asm("mov.b64 %0, {%1, %2};" : "=l"(r) : "f"(lo), "f"(hi));
    return r;
}
__device__ __forceinline__ u64 fma2(u64 a, u64 b, u64 c) {
    u64 d;
    asm("fma.rn.f32x2 %0, %1, %2, %3;" : "=l"(d) : "l"(a), "l"(b), "l"(c));
    return d;
}
__device__ __forceinline__ void unpack2(u64 v, float& lo, float& hi) {
    asm("mov.b64 {%0, %1}, %2;" : "=f"(lo), "=f"(hi) : "l"(v));
}

// ---------------------------------------------------------------------------
// Kernel 1: splat parameters (tiny)
// ---------------------------------------------------------------------------
__global__ void params_kernel(const float* __restrict__ sc, const float* __restrict__ sd,
                              const float* __restrict__ ls, const float* __restrict__ la,
                              const float* __restrict__ ms, const float* __restrict__ temp) {
    const int tid = threadIdx.x;
    const float sig = 1.0f / (1.0f + expf(-ms[0]));
    const float mv = sig * 0.2f;
    for (int i = tid; i < H_ * S_ * HD_; i += 256)
        g_centers[i] = sc[i] + sd[i] * mv;
    {
        float scale = fminf(fmaxf(expf(ls[tid]), 0.01f), 2.0f);
        g_invvar[tid] = -0.5f / (scale * scale + 1e-8f);
        g_amp[tid] = fminf(fmaxf(expf(la[tid]), 1e-6f), 10.0f);
    }
    __syncthreads();
    if (tid < H_) {
        float t = fminf(fmaxf(temp[0], 0.1f), 10.0f);
        float it = 1.0f / t;
        float ssum = 0.0f;
        for (int s = 0; s < S_; s++) ssum += g_amp[tid * S_ + s];
        g_shift[tid] = 0.5f * ssum * it;
        if (tid == 0) g_invtemp = it;
    }
}

// ---------------------------------------------------------------------------
// NT SGEMM body  C[m,n] = sum_k A[m,k] * Bw[n,k]
// 128x128 tile, BK=16, 256 threads, 8x8/thread via f32x2 pairs.
// ---------------------------------------------------------------------------
__device__ __forceinline__ void sgemm_nt_body(
    const float* __restrict__ A, const float* __restrict__ Bw,
    float* __restrict__ C, int M, int N, int K)
{
    __shared__ float As[16][132];
    __shared__ float Bs[16][132];
    const int tid = threadIdx.x;
    const int tx = tid & 15, ty = tid >> 4;
    const int m0 = blockIdx.y * 128, n0 = blockIdx.x * 128;
    const int lr = tid >> 2;
    const int lc = (tid & 3) << 2;

    const float* Ap0 = A + (size_t)(m0 + lr) * K + lc;
    const float* Ap1 = A + (size_t)(m0 + lr + 64) * K + lc;
    const float* Bp0 = Bw + (size_t)(n0 + lr) * K + lc;
    const float* Bp1 = Bw + (size_t)(n0 + lr + 64) * K + lc;

    u64 acc[8][4];
#pragma unroll
    for (int i = 0; i < 8; i++)
#pragma unroll
        for (int j = 0; j < 4; j++) acc[i][j] = 0ull;

    float4 ra0 = *(const float4*)Ap0;
    float4 ra1 = *(const float4*)Ap1;
    float4 rb0 = *(const float4*)Bp0;
    float4 rb1 = *(const float4*)Bp1;

    for (int k0 = 0; k0 < K; k0 += 16) {
        As[lc + 0][lr] = ra0.x; As[lc + 1][lr] = ra0.y; As[lc + 2][lr] = ra0.z; As[lc + 3][lr] = ra0.w;
        As[lc + 0][lr + 64] = ra1.x; As[lc + 1][lr + 64] = ra1.y; As[lc + 2][lr + 64] = ra1.z; As[lc + 3][lr + 64] = ra1.w;
        Bs[lc + 0][lr] = rb0.x; Bs[lc + 1][lr] = rb0.y; Bs[lc + 2][lr] = rb0.z; Bs[lc + 3][lr] = rb0.w;
        Bs[lc + 0][lr + 64] = rb1.x; Bs[lc + 1][lr + 64] = rb1.y; Bs[lc + 2][lr + 64] = rb1.z; Bs[lc + 3][lr + 64] = rb1.w;
        __syncthreads();

        if (k0 + 16 < K) {
            ra0 = *(const float4*)(Ap0 + k0 + 16);
            ra1 = *(const float4*)(Ap1 + k0 + 16);
            rb0 = *(const float4*)(Bp0 + k0 + 16);
            rb1 = *(const float4*)(Bp1 + k0 + 16);
        }

#pragma unroll
        for (int k = 0; k < 16; k++) {
            float av[8];
            *(float4*)&av[0] = *(const float4*)&As[k][ty * 8];
            *(float4*)&av[4] = *(const float4*)&As[k][ty * 8 + 4];
            const u64* bp = (const u64*)&Bs[k][tx * 8];
            u64 b0 = bp[0], b1 = bp[1], b2 = bp[2], b3 = bp[3];
#pragma unroll
            for (int i = 0; i < 8; i++) {
                u64 ap = pack2(av[i], av[i]);
                acc[i][0] = fma2(ap, b0, acc[i][0]);
                acc[i][1] = fma2(ap, b1, acc[i][1]);
                acc[i][2] = fma2(ap, b2, acc[i][2]);
                acc[i][3] = fma2(ap, b3, acc[i][3]);
            }
        }
        __syncthreads();
    }

#pragma unroll
    for (int i = 0; i < 8; i++) {
        float out[8];
#pragma unroll
        for (int j = 0; j < 4; j++) unpack2(acc[i][j], out[2 * j], out[2 * j + 1]);
        float* cp = C + (size_t)(m0 + ty * 8 + i) * N + n0 + tx * 8;
        *(float4*)cp       = make_float4(out[0], out[1], out[2], out[3]);
        *(float4*)(cp + 4) = make_float4(out[4], out[5], out[6], out[7]);
    }
}

__global__ __launch_bounds__(256) void qkv_gemm_kernel(
    const float* __restrict__ x, const float* __restrict__ qkv_w) {
    sgemm_nt_body(x, qkv_w, g_qkv, BT_, N3D_, D_);
}
__global__ __launch_bounds__(256) void out_gemm_kernel(
    const float* __restrict__ out_w, float* __restrict__ out) {
    sgemm_nt_body(g_attno, out_w, out, BT_, D_, D_);
}

// ---------------------------------------------------------------------------
// Kernel 3: splat weights.  block = 16 tokens x 16 splats, grid (T/16, B*H)
// ---------------------------------------------------------------------------
__global__ __launch_bounds__(256) void splat_weights_kernel() {
    __shared__ float qsm[16][65], ksm2[16][65], csm[16][65];
    __shared__ float ivv[16], amps[16];
    const int tid = threadIdx.x;
    const int bh = blockIdx.y, b = bh >> 4, h = bh & 15;
    const int t0 = blockIdx.x * 16;

    for (int idx = tid; idx < 16 * 64; idx += 256) {
        int s = idx >> 6, d = idx & 63;
        csm[s][d] = g_centers[(h * 16 + s) * 64 + d];
    }
    if (tid < 16) { ivv[tid] = g_invvar[h * 16 + tid]; amps[tid] = g_amp[h * 16 + tid]; }
    for (int idx = tid; idx < 16 * 64; idx += 256) {
        int tt = idx >> 6, d = idx & 63;
        size_t base = ((size_t)(b * T_ + t0 + tt) * 3) * D_ + h * 64 + d;
        qsm[tt][d] = g_qkv[base];
        ksm2[tt][d] = g_qkv[base + D_];
    }
    __syncthreads();

    const int s = tid & 15, tt = tid >> 4;
    float dq = 0.0f, dk = 0.0f;
#pragma unroll
    for (int d = 0; d < 64; d++) {
        float c = csm[s][d];
        float x1 = qsm[tt][d] - c; dq = fmaf(x1, x1, dq);
        float x2 = ksm2[tt][d] - c; dk = fmaf(x2, x2, dk);
    }
    size_t oidx = ((size_t)bh * T_ + t0 + tt) * S_ + s;
    g_qwa[oidx] = __expf(dq * ivv[s]) * amps[s];
    g_kw[oidx]  = __expf(dk * ivv[s]);
}

// ---------------------------------------------------------------------------
// Kernel 4: flash attention over splat weights (crossbar-optimized v2).
// j-tile = 64. Stage 1: 8m x 4j per thread (256 threads cover 128x64).
// Stage 2: 8m x 8d per thread, 128 threads per k-half (2-way k-split),
//          reduced once at the end through smem.
// Es uses XOR swizzle (col ^ ((row&7)<<4)) for conflict-free stores.
// Dynamic smem: 73216 B.
// ---------------------------------------------------------------------------
#define QS(s, m)  smf[(s) * 132 + (m)]
#define KSH(s, j) smf[16 * 132 + (s) * 68 + (j)]
#define ES(j, m)  smf[16 * 132 + 16 * 68 + (j) * 132 + (m)]
#define VS(j, d)  smf[16 * 132 + 16 * 68 + 64 * 132 + (j) * 68 + (d)]
#define PSU(m, g) smf[16 * 132 + 16 * 68 + 64 * 132 + 64 * 68 + (m) * 17 + (g)]
#define RSU(m)    smf[16 * 132 + 16 * 68 + 64 * 132 + 64 * 68 + 128 * 17 + (m)]
#define FLASH_SMEM_FLOATS (16 * 132 + 16 * 68 + 64 * 132 + 64 * 68 + 128 * 17 + 128)

__global__ __launch_bounds__(256, 2) void flash_kernel() {
    extern __shared__ float smf[];

    const int tid = threadIdx.x;
    const int bh = blockIdx.y, b = bh >> 4, h = bh & 15;
    const int i0 = blockIdx.x * 128;
    const float* qwa = g_qwa + ((size_t)bh * T_ + i0) * S_;
    const float* kwp = g_kw + (size_t)bh * T_ * S_;
    const float* vp  = g_qkv + ((size_t)b * T_ * 3 + 2) * D_ + h * HD_;  // row stride 3072
    const float invtemp = g_invtemp;
    const float shift = g_shift[h];

    // stage-1 ownership: 8m x 4j
    const int mg = tid >> 4;          // 0..15 -> m = mg*8
    const int jg = tid & 15;          // 0..15 -> j = jg*4
    // stage-2 ownership: 8m x 8d, 2-way k-split
    const int pos = tid & 127;
    const int ks  = tid >> 7;         // 0/1: k half
    const int ty2 = pos >> 3;         // 0..15 -> m = ty2*8
    const int tx2 = pos & 7;          // 0..7  -> d = tx2*8

    // load qwa tile transposed [s][m]
    for (int f = tid; f < 512; f += 256) {
        int r = f >> 2, c4 = (f & 3) << 2;
        float4 v = *(const float4*)(qwa + r * 16 + c4);
        QS(c4 + 0, r) = v.x; QS(c4 + 1, r) = v.y; QS(c4 + 2, r) = v.z; QS(c4 + 3, r) = v.w;
    }
    for (int f = tid; f < 128 * 17; f += 256) PSU(0, f) = 0.0f;

    u64 o2[4][8];                     // [m-pair][d]
#pragma unroll
    for (int i = 0; i < 4; i++)
#pragma unroll
        for (int j = 0; j < 8; j++) o2[i][j] = 0ull;

    for (int j0 = 0; j0 < T_; j0 += 64) {
        // kw tile 64x16 transposed -> KSH[s][j]
        {
            int r = tid >> 2, c4 = (tid & 3) << 2;
            float4 v = *(const float4*)(kwp + (size_t)(j0 + r) * 16 + c4);
            KSH(c4 + 0, r) = v.x; KSH(c4 + 1, r) = v.y; KSH(c4 + 2, r) = v.z; KSH(c4 + 3, r) = v.w;
        }
        // V tile 64x64
#pragma unroll
        for (int u = 0; u < 4; u++) {
            int f = tid + u * 256;
            int r = f >> 4, c4 = (f & 15) << 2;
            *(float4*)&VS(r, c4) = *(const float4*)(vp + (size_t)(j0 + r) * 3072 + c4);
        }
        __syncthreads();

        // ---- stage 1: logits for 8m x 4j, exp, store E tile (+ row sums)
        {
            u64 l2[4][4];
#pragma unroll
            for (int jj = 0; jj < 4; jj++)
#pragma unroll
                for (int mi = 0; mi < 4; mi++) l2[jj][mi] = 0ull;

#pragma unroll
            for (int s = 0; s < 16; s++) {
                const u64* ap = (const u64*)&QS(s, mg * 8);
                u64 a0 = ap[0], a1 = ap[1], a2 = ap[2], a3 = ap[3];
                float4 kv = *(const float4*)&KSH(s, jg * 4);
                u64 b0 = pack2(kv.x, kv.x), b1 = pack2(kv.y, kv.y);
                u64 b2 = pack2(kv.z, kv.z), b3 = pack2(kv.w, kv.w);
                l2[0][0] = fma2(a0, b0, l2[0][0]); l2[0][1] = fma2(a1, b0, l2[0][1]);
                l2[0][2] = fma2(a2, b0, l2[0][2]); l2[0][3] = fma2(a3, b0, l2[0][3]);
                l2[1][0] = fma2(a0, b1, l2[1][0]); l2[1][1] = fma2(a1, b1, l2[1][1]);
                l2[1][2] = fma2(a2, b1, l2[1][2]); l2[1][3] = fma2(a3, b1, l2[1][3]);
                l2[2][0] = fma2(a0, b2, l2[2][0]); l2[2][1] = fma2(a1, b2, l2[2][1]);
                l2[2][2] = fma2(a2, b2, l2[2][2]); l2[2][3] = fma2(a3, b2, l2[2][3]);
                l2[3][0] = fma2(a0, b3, l2[3][0]); l2[3][1] = fma2(a1, b3, l2[3][1]);
                l2[3][2] = fma2(a2, b3, l2[3][2]); l2[3][3] = fma2(a3, b3, l2[3][3]);
            }
            float rs[8];
#pragma unroll
            for (int rr = 0; rr < 8; rr++) rs[rr] = 0.0f;
#pragma unroll
            for (int jj = 0; jj < 4; jj++) {
                float p[8];
#pragma unroll
                for (int mi = 0; mi < 4; mi++) {
                    float lo, hi;
                    unpack2(l2[jj][mi], lo, hi);
                    float e0 = __expf(fmaf(lo, invtemp, -shift));
                    float e1 = __expf(fmaf(hi, invtemp, -shift));
                    p[2 * mi] = e0; p[2 * mi + 1] = e1;
                    rs[2 * mi] += e0; rs[2 * mi + 1] += e1;
                }
                int row = jg * 4 + jj;
                int base = (mg * 8) ^ ((row & 7) << 4);   // swizzled column
                *(float4*)&ES(row, base)     = make_float4(p[0], p[1], p[2], p[3]);
                *(float4*)&ES(row, base + 4) = make_float4(p[4], p[5], p[6], p[7]);
            }
#pragma unroll
            for (int rr = 0; rr < 8; rr++) PSU(mg * 8 + rr, jg) += rs[rr];
        }
        __syncthreads();

        // ---- stage 2: o += E^T(j,m) * V(j,d), 8m x 8d, this thread's k half
#pragma unroll 4
        for (int kk = 0; kk < 32; kk++) {
            int k = ks * 32 + kk;
            int abase = (ty2 * 8) ^ ((k & 7) << 4);
            const u64* ap = (const u64*)&ES(k, abase);
            u64 a0 = ap[0], a1 = ap[1], a2 = ap[2], a3 = ap[3];
            float4 bv0 = *(const float4*)&VS(k, tx2 * 8);
            float4 bv1 = *(const float4*)&VS(k, tx2 * 8 + 4);
            u64 b0 = pack2(bv0.x, bv0.x), b1 = pack2(bv0.y, bv0.y);
            u64 b2 = pack2(bv0.z, bv0.z), b3 = pack2(bv0.w, bv0.w);
            u64 b4 = pack2(bv1.x, bv1.x), b5 = pack2(bv1.y, bv1.y);
            u64 b6 = pack2(bv1.z, bv1.z), b7 = pack2(bv1.w, bv1.w);
            o2[0][0] = fma2(a0, b0, o2[0][0]); o2[0][1] = fma2(a0, b1, o2[0][1]);
            o2[0][2] = fma2(a0, b2, o2[0][2]); o2[0][3] = fma2(a0, b3, o2[0][3]);
            o2[0][4] = fma2(a0, b4, o2[0][4]); o2[0][5] = fma2(a0, b5, o2[0][5]);
            o2[0][6] = fma2(a0, b6, o2[0][6]); o2[0][7] = fma2(a0, b7, o2[0][7]);
            o2[1][0] = fma2(a1, b0, o2[1][0]); o2[1][1] = fma2(a1, b1, o2[1][1]);
            o2[1][2] = fma2(a1, b2, o2[1][2]); o2[1][3] = fma2(a1, b3, o2[1][3]);
            o2[1][4] = fma2(a1, b4, o2[1][4]); o2[1][5] = fma2(a1, b5, o2[1][5]);
            o2[1][6] = fma2(a1, b6, o2[1][6]); o2[1][7] = fma2(a1, b7, o2[1][7]);
            o2[2][0] = fma2(a2, b0, o2[2][0]); o2[2][1] = fma2(a2, b1, o2[2][1]);
            o2[2][2] = fma2(a2, b2, o2[2][2]); o2[2][3] = fma2(a2, b3, o2[2][3]);
            o2[2][4] = fma2(a2, b4, o2[2][4]); o2[2][5] = fma2(a2, b5, o2[2][5]);
            o2[2][6] = fma2(a2, b6, o2[2][6]); o2[2][7] = fma2(a2, b7, o2[2][7]);
            o2[3][0] = fma2(a3, b0, o2[3][0]); o2[3][1] = fma2(a3, b1, o2[3][1]);
            o2[3][2] = fma2(a3, b2, o2[3][2]); o2[3][3] = fma2(a3, b3, o2[3][3]);
            o2[3][4] = fma2(a3, b4, o2[3][4]); o2[3][5] = fma2(a3, b5, o2[3][5]);
            o2[3][6] = fma2(a3, b6, o2[3][6]); o2[3][7] = fma2(a3, b7, o2[3][7]);
        }
        __syncthreads();
    }

    // ---- k-split reduction (k-half 1 spills to smem; half 0 accumulates)
    float* red = &ES(0, 0);           // 8448 floats available, need 8192
    if (ks == 1) {
#pragma unroll
        for (int mi = 0; mi < 4; mi++)
#pragma unroll
            for (int dj = 0; dj < 8; dj++) {
                float lo, hi;
                unpack2(o2[mi][dj], lo, hi);
                red[(mi * 16 + dj) * 128 + pos]     = lo;
                red[(mi * 16 + 8 + dj) * 128 + pos] = hi;
            }
    } else {
        float s = 0.0f;
#pragma unroll
        for (int x = 0; x < 16; x++) s += PSU(pos, x);
        RSU(pos) = s;
    }
    __syncthreads();

    if (ks == 0) {
#pragma unroll
        for (int mi = 0; mi < 4; mi++) {
            int m = ty2 * 8 + 2 * mi;
            float inv0 = 1.0f / RSU(m), inv1 = 1.0f / RSU(m + 1);
            float r0[8], r1[8];
#pragma unroll
            for (int dj = 0; dj < 8; dj++) {
                float lo, hi;
                unpack2(o2[mi][dj], lo, hi);
                lo += red[(mi * 16 + dj) * 128 + pos];
                hi += red[(mi * 16 + 8 + dj) * 128 + pos];
                r0[dj] = lo * inv0; r1[dj] = hi * inv1;
            }
            float* outp = g_attno + ((size_t)(b * T_) + i0 + m) * D_ + h * HD_ + tx2 * 8;
            *(float4*)outp            = make_float4(r0[0], r0[1], r0[2], r0[3]);
            *(float4*)(outp + 4)      = make_float4(r0[4], r0[5], r0[6], r0[7]);
            *(float4*)(outp + D_)     = make_float4(r1[0], r1[1], r1[2], r1[3]);
            *(float4*)(outp + D_ + 4) = make_float4(r1[4], r1[5], r1[6], r1[7]);
        }
    }
}

// ---------------------------------------------------------------------------
// Launch
// ---------------------------------------------------------------------------
extern "C" void kernel_launch(void* const* d_in, const int* in_sizes, int n_in,
                              void* d_out, int out_size) {
    const float* x     = (const float*)d_in[0];
    const float* sc    = (const float*)d_in[1];
    const float* sd    = (const float*)d_in[2];
    const float* ls    = (const float*)d_in[3];
    const float* la    = (const float*)d_in[4];
    const float* ms    = (const float*)d_in[5];
    const float* temp  = (const float*)d_in[6];
    const float* qkv_w = (const float*)d_in[7];
    const float* out_w = (const float*)d_in[8];
    float* out = (float*)d_out;

    const int flash_smem = FLASH_SMEM_FLOATS * 4;   // 73216 B
    cudaFuncSetAttribute(flash_kernel, cudaFuncAttributeMaxDynamicSharedMemorySize, flash_smem);

    params_kernel<<<1, 256>>>(sc, sd, ls, la, ms, temp);
    qkv_gemm_kernel<<<dim3(N3D_ / 128, BT_ / 128), 256>>>(x, qkv_w);
    splat_weights_kernel<<<dim3(T_ / 16, B_ * H_), 256>>>();
    flash_kernel<<<dim3(T_ / 128, B_ * H_), 256, flash_smem>>>();
    out_gemm_kernel<<<dim3(D_ / 128, BT_ / 128), 256>>>(out_w, out);
}

// round 5
// speedup vs baseline: 1.4090x; 1.4090x over previous
#include <cuda_runtime.h>
#include <cuda_bf16.h>

// Problem constants
#define B_   2
#define T_   2048
#define D_   1024
#define H_   16
#define S_   16
#define HD_  64
#define BT_  (B_ * T_)     // 4096
#define N3D_ (3 * D_)      // 3072

// ---------------------------------------------------------------------------
// Workspaces (device globals — no allocation allowed)
// ---------------------------------------------------------------------------
__device__ float g_qkv[BT_ * N3D_];          // (b,t,{q,k,v},h,hd)
__device__ float g_attno[BT_ * D_];          // attention output (b,t,h,hd)
__device__ float g_qwa[B_ * H_ * T_ * S_];   // q splat weights * amplitude
__device__ float g_kw [B_ * H_ * T_ * S_];   // k splat weights
__device__ float g_centers[H_ * S_ * HD_];
__device__ float g_invvar[H_ * S_];
__device__ float g_amp[H_ * S_];
__device__ float g_shift[H_];
__device__ float g_invtemp;

typedef unsigned long long u64;

// ---------------------------------------------------------------------------
// f32x2 helpers (flash kernel)
// ---------------------------------------------------------------------------
__device__ __forceinline__ u64 pack2(float lo, float hi) {
    u64 r; asm("mov.b64 %0, {%1, %2};" : "=l"(r) : "f"(lo), "f"(hi)); return r;
}
__device__ __forceinline__ u64 fma2(u64 a, u64 b, u64 c) {
    u64 d; asm("fma.rn.f32x2 %0, %1, %2, %3;" : "=l"(d) : "l"(a), "l"(b), "l"(c)); return d;
}
__device__ __forceinline__ void unpack2(u64 v, float& lo, float& hi) {
    asm("mov.b64 {%0, %1}, %2;" : "=f"(lo), "=f"(hi) : "l"(v));
}

// ---------------------------------------------------------------------------
// mma.sync helpers (sm_80+ path; tcgen05 not available: PTX target lacks 'a')
// ---------------------------------------------------------------------------
__device__ __forceinline__ unsigned smem_u32(const void* p) {
    unsigned a;
    asm("{ .reg .u64 t; cvta.to.shared.u64 t, %1; cvt.u32.u64 %0, t; }" : "=r"(a) : "l"(p));
    return a;
}
__device__ __forceinline__ void ldsm_x4(unsigned* r, unsigned addr) {
    asm volatile("ldmatrix.sync.aligned.m8n8.x4.shared.b16 {%0,%1,%2,%3}, [%4];"
                 : "=r"(r[0]), "=r"(r[1]), "=r"(r[2]), "=r"(r[3]) : "r"(addr));
}
__device__ __forceinline__ void ldsm_x2(unsigned* r, unsigned addr) {
    asm volatile("ldmatrix.sync.aligned.m8n8.x2.shared.b16 {%0,%1}, [%2];"
                 : "=r"(r[0]), "=r"(r[1]) : "r"(addr));
}
__device__ __forceinline__ void mma_bf16(float* c, const unsigned* a, const unsigned* b) {
    asm volatile("mma.sync.aligned.m16n8k16.row.col.f32.bf16.bf16.f32 "
                 "{%0,%1,%2,%3}, {%4,%5,%6,%7}, {%8,%9}, {%0,%1,%2,%3};"
                 : "+f"(c[0]), "+f"(c[1]), "+f"(c[2]), "+f"(c[3])
                 : "r"(a[0]), "r"(a[1]), "r"(a[2]), "r"(a[3]), "r"(b[0]), "r"(b[1]));
}
__device__ __forceinline__ unsigned swz(unsigned off) {
    return off ^ (((off >> 7) & 3u) << 4);
}

// ---------------------------------------------------------------------------
// Kernel 1: splat parameters (tiny)
// ---------------------------------------------------------------------------
__global__ void params_kernel(const float* __restrict__ sc, const float* __restrict__ sd,
                              const float* __restrict__ ls, const float* __restrict__ la,
                              const float* __restrict__ ms, const float* __restrict__ temp) {
    const int tid = threadIdx.x;
    const float sig = 1.0f / (1.0f + expf(-ms[0]));
    const float mv = sig * 0.2f;
    for (int i = tid; i < H_ * S_ * HD_; i += 256)
        g_centers[i] = sc[i] + sd[i] * mv;
    {
        float scale = fminf(fmaxf(expf(ls[tid]), 0.01f), 2.0f);
        g_invvar[tid] = -0.5f / (scale * scale + 1e-8f);
        g_amp[tid] = fminf(fmaxf(expf(la[tid]), 1e-6f), 10.0f);
    }
    __syncthreads();
    if (tid < H_) {
        float t = fminf(fmaxf(temp[0], 0.1f), 10.0f);
        float it = 1.0f / t;
        float ssum = 0.0f;
        for (int s = 0; s < S_; s++) ssum += g_amp[tid * S_ + s];
        g_shift[tid] = 0.5f * ssum * it;
        if (tid == 0) g_invtemp = it;
    }
}

// ---------------------------------------------------------------------------
// Split-bf16 tensor-core NT GEMM: C[m,n] = sum_k A[m,k]*Bw[n,k]
// Block 128x128, BK=32, double-buffered smem (2 x 32KB), 256 threads.
// Warp grid 2(m) x 4(n); warp tile 64x32 = 4x4 m16n8k16 subtiles.
// fp32 = hi(bf16) + lo(bf16); products hh + hl + lh (ll ~2^-18, dropped).
// smem per stage: Ahi[128][32] | Alo | Bhi[128][32] | Blo  (bf16, 64B rows,
// swizzled with off ^ (((off>>7)&3)<<4) for conflict-free ldmatrix).
// ---------------------------------------------------------------------------
#define TCG_STAGE 32768
#define TCG_SMEM  (2 * TCG_STAGE)

__device__ __forceinline__ void cvt_store16(const float* v, char* hi_b, char* lo_b, int r, int h) {
#pragma unroll
    for (int i = 0; i < 8; i++) {
        float x0 = v[2 * i], x1 = v[2 * i + 1];
        __nv_bfloat16 h0 = __float2bfloat16(x0), h1 = __float2bfloat16(x1);
        __nv_bfloat16 l0 = __float2bfloat16(x0 - __bfloat162float(h0));
        __nv_bfloat16 l1 = __float2bfloat16(x1 - __bfloat162float(h1));
        unsigned off = swz((unsigned)(r * 64 + h * 32 + i * 4));
        *(__nv_bfloat162*)(hi_b + off) = __nv_bfloat162(h0, h1);
        *(__nv_bfloat162*)(lo_b + off) = __nv_bfloat162(l0, l1);
    }
}

__device__ __forceinline__ void tc_load_chunk(
    const float* __restrict__ A, const float* __restrict__ Bw, int K,
    char* stage, int c, int m0, int n0, int tid)
{
    const int r = tid >> 1, h = tid & 1;
    const float* ap = A + (size_t)(m0 + r) * K + c * 32 + h * 16;
    const float* bp = Bw + (size_t)(n0 + r) * K + c * 32 + h * 16;
    float va[16], vb[16];
#pragma unroll
    for (int i = 0; i < 4; i++) *(float4*)&va[i * 4] = *(const float4*)(ap + i * 4);
#pragma unroll
    for (int i = 0; i < 4; i++) *(float4*)&vb[i * 4] = *(const float4*)(bp + i * 4);
    cvt_store16(va, stage,          stage + 8192,  r, h);
    cvt_store16(vb, stage + 16384,  stage + 24576, r, h);
}

__device__ __forceinline__ void tc_gemm_nt_body(
    const float* __restrict__ A, const float* __restrict__ Bw,
    float* __restrict__ C, int N, int K)
{
    extern __shared__ char gs[];
    const int tid = threadIdx.x;
    const int m0 = blockIdx.y * 128, n0 = blockIdx.x * 128;
    const int NC = K / 32;
    const unsigned sbase = smem_u32(gs);

    const int warp = tid >> 5, lane = tid & 31;
    const int wm = warp >> 2, wn = warp & 3;        // 2 x 4 warp grid
    // lane-invariant ldmatrix address components
    const int a_row = (lane & 7) + ((lane >> 3) & 1) * 8;   // 0..15
    const int a_kb  = (lane >> 4) * 16;                     // 0 or 16 bytes
    const int b_row = lane & 7;
    const int b_kb  = ((lane >> 3) & 1) * 16;

    float acc[4][4][4];
#pragma unroll
    for (int i = 0; i < 4; i++)
#pragma unroll
        for (int j = 0; j < 4; j++)
#pragma unroll
            for (int q = 0; q < 4; q++) acc[i][j][q] = 0.0f;

    tc_load_chunk(A, Bw, K, gs, 0, m0, n0, tid);

    for (int c = 0; c < NC; c++) {
        const int s = c & 1;
        __syncthreads();
        const unsigned stA_hi = sbase + s * TCG_STAGE;
        const unsigned stA_lo = stA_hi + 8192;
        const unsigned stB_hi = stA_hi + 16384;
        const unsigned stB_lo = stA_hi + 24576;

#pragma unroll
        for (int kh = 0; kh < 2; kh++) {
            unsigned a[4][4], bh[4][2], bl[4][2];
#pragma unroll
            for (int mt = 0; mt < 4; mt++) {
                unsigned off = (unsigned)((wm * 64 + mt * 16 + a_row) * 64 + kh * 32 + a_kb);
                ldsm_x4(a[mt], stA_hi + swz(off));
            }
#pragma unroll
            for (int nt = 0; nt < 4; nt++) {
                unsigned off = (unsigned)((wn * 32 + nt * 8 + b_row) * 64 + kh * 32 + b_kb);
                ldsm_x2(bh[nt], stB_hi + swz(off));
                ldsm_x2(bl[nt], stB_lo + swz(off));
            }
            // hh
#pragma unroll
            for (int mt = 0; mt < 4; mt++)
#pragma unroll
                for (int nt = 0; nt < 4; nt++) mma_bf16(acc[mt][nt], a[mt], bh[nt]);
            // hl
#pragma unroll
            for (int mt = 0; mt < 4; mt++)
#pragma unroll
                for (int nt = 0; nt < 4; nt++) mma_bf16(acc[mt][nt], a[mt], bl[nt]);
            // lh: reload A as lo
#pragma unroll
            for (int mt = 0; mt < 4; mt++) {
                unsigned off = (unsigned)((wm * 64 + mt * 16 + a_row) * 64 + kh * 32 + a_kb);
                ldsm_x4(a[mt], stA_lo + swz(off));
            }
#pragma unroll
            for (int mt = 0; mt < 4; mt++)
#pragma unroll
                for (int nt = 0; nt < 4; nt++) mma_bf16(acc[mt][nt], a[mt], bh[nt]);
        }

        if (c + 1 < NC)
            tc_load_chunk(A, Bw, K, gs + (s ^ 1) * TCG_STAGE, c + 1, m0, n0, tid);
    }

    // Epilogue
    const int qrow = lane >> 2, qcol = (lane & 3) * 2;
#pragma unroll
    for (int mt = 0; mt < 4; mt++) {
#pragma unroll
        for (int nt = 0; nt < 4; nt++) {
            int m = m0 + wm * 64 + mt * 16 + qrow;
            int n = n0 + wn * 32 + nt * 8 + qcol;
            *(float2*)&C[(size_t)m * N + n]       = make_float2(acc[mt][nt][0], acc[mt][nt][1]);
            *(float2*)&C[(size_t)(m + 8) * N + n] = make_float2(acc[mt][nt][2], acc[mt][nt][3]);
        }
    }
}

__global__ __launch_bounds__(256, 2)
void qkv_gemm_tc(const float* __restrict__ x, const float* __restrict__ qkv_w) {
    tc_gemm_nt_body(x, qkv_w, g_qkv, N3D_, D_);
}
__global__ __launch_bounds__(256, 2)
void out_gemm_tc(const float* __restrict__ out_w, float* __restrict__ out) {
    tc_gemm_nt_body(g_attno, out_w, out, D_, D_);
}

// ---------------------------------------------------------------------------
// Kernel 3: splat weights.  block = 16 tokens x 16 splats, grid (T/16, B*H)
// ---------------------------------------------------------------------------
__global__ __launch_bounds__(256) void splat_weights_kernel() {
    __shared__ float qsm[16][65], ksm2[16][65], csm[16][65];
    __shared__ float ivv[16], amps[16];
    const int tid = threadIdx.x;
    const int bh = blockIdx.y, b = bh >> 4, h = bh & 15;
    const int t0 = blockIdx.x * 16;

    for (int idx = tid; idx < 16 * 64; idx += 256) {
        int s = idx >> 6, d = idx & 63;
        csm[s][d] = g_centers[(h * 16 + s) * 64 + d];
    }
    if (tid < 16) { ivv[tid] = g_invvar[h * 16 + tid]; amps[tid] = g_amp[h * 16 + tid]; }
    for (int idx = tid; idx < 16 * 64; idx += 256) {
        int tt = idx >> 6, d = idx & 63;
        size_t base = ((size_t)(b * T_ + t0 + tt) * 3) * D_ + h * 64 + d;
        qsm[tt][d] = g_qkv[base];
        ksm2[tt][d] = g_qkv[base + D_];
    }
    __syncthreads();

    const int s = tid & 15, tt = tid >> 4;
    float dq = 0.0f, dk = 0.0f;
#pragma unroll
    for (int d = 0; d < 64; d++) {
        float c = csm[s][d];
        float x1 = qsm[tt][d] - c; dq = fmaf(x1, x1, dq);
        float x2 = ksm2[tt][d] - c; dk = fmaf(x2, x2, dk);
    }
    size_t oidx = ((size_t)bh * T_ + t0 + tt) * S_ + s;
    g_qwa[oidx] = __expf(dq * ivv[s]) * amps[s];
    g_kw[oidx]  = __expf(dk * ivv[s]);
}

// ---------------------------------------------------------------------------
// Kernel 4: flash attention over splat weights (R2 proven version).
// ---------------------------------------------------------------------------
__global__ __launch_bounds__(256) void flash_kernel() {
    __shared__ float qs[16][128];
    __shared__ float ksh[16][36];
    __shared__ float Es[32][132];
    __shared__ float Vs[32][68];
    __shared__ float psum[128][17];
    __shared__ float rsum[128];

    const int tid = threadIdx.x;
    const int bh = blockIdx.y, b = bh >> 4, h = bh & 15;
    const int i0 = blockIdx.x * 128;
    const float* qwa = g_qwa + ((size_t)bh * T_ + i0) * S_;
    const float* kwp = g_kw + (size_t)bh * T_ * S_;
    const float* vp  = g_qkv + ((size_t)b * T_ * 3 + 2) * D_ + h * HD_;
    const float invtemp = g_invtemp;
    const float shift = g_shift[h];

    for (int f = tid; f < 512; f += 256) {
        int r = f >> 2, c4 = (f & 3) << 2;
        float4 v = *(const float4*)(qwa + r * 16 + c4);
        qs[c4 + 0][r] = v.x; qs[c4 + 1][r] = v.y; qs[c4 + 2][r] = v.z; qs[c4 + 3][r] = v.w;
    }
    for (int f = tid; f < 128 * 17; f += 256) (&psum[0][0])[f] = 0.0f;

    const int tx = tid & 15, ty = tid >> 4;
    u64 o2[4][4];
#pragma unroll
    for (int i = 0; i < 4; i++)
#pragma unroll
        for (int j = 0; j < 4; j++) o2[i][j] = 0ull;

    for (int j0 = 0; j0 < T_; j0 += 32) {
        if (tid < 128) {
            int r = tid >> 2, c4 = (tid & 3) << 2;
            float4 v = *(const float4*)(kwp + (size_t)(j0 + r) * 16 + c4);
            ksh[c4 + 0][r] = v.x; ksh[c4 + 1][r] = v.y; ksh[c4 + 2][r] = v.z; ksh[c4 + 3][r] = v.w;
        }
#pragma unroll
        for (int u = 0; u < 2; u++) {
            int f = tid + u * 256;
            int r = f >> 4, c4 = (f & 15) << 2;
            *(float4*)&Vs[r][c4] = *(const float4*)(vp + (size_t)(j0 + r) * 3072 + c4);
        }
        __syncthreads();

        {
            u64 l2[2][4];
#pragma unroll
            for (int jj = 0; jj < 2; jj++)
#pragma unroll
                for (int mi = 0; mi < 4; mi++) l2[jj][mi] = 0ull;

#pragma unroll
            for (int s = 0; s < 16; s++) {
                const u64* ap = (const u64*)&qs[s][ty * 8];
                u64 a0 = ap[0], a1 = ap[1], a2 = ap[2], a3 = ap[3];
                float bk0 = ksh[s][tx * 2], bk1 = ksh[s][tx * 2 + 1];
                u64 b0 = pack2(bk0, bk0), b1 = pack2(bk1, bk1);
                l2[0][0] = fma2(a0, b0, l2[0][0]);
                l2[0][1] = fma2(a1, b0, l2[0][1]);
                l2[0][2] = fma2(a2, b0, l2[0][2]);
                l2[0][3] = fma2(a3, b0, l2[0][3]);
                l2[1][0] = fma2(a0, b1, l2[1][0]);
                l2[1][1] = fma2(a1, b1, l2[1][1]);
                l2[1][2] = fma2(a2, b1, l2[1][2]);
                l2[1][3] = fma2(a3, b1, l2[1][3]);
            }
            float p[2][8], rs[8];
#pragma unroll
            for (int rr = 0; rr < 8; rr++) rs[rr] = 0.0f;
#pragma unroll
            for (int jj = 0; jj < 2; jj++) {
#pragma unroll
                for (int mi = 0; mi < 4; mi++) {
                    float lo, hi;
                    unpack2(l2[jj][mi], lo, hi);
                    float e0 = __expf(fmaf(lo, invtemp, -shift));
                    float e1 = __expf(fmaf(hi, invtemp, -shift));
                    p[jj][2 * mi] = e0; p[jj][2 * mi + 1] = e1;
                    rs[2 * mi] += e0; rs[2 * mi + 1] += e1;
                }
                *(float4*)&Es[tx * 2 + jj][ty * 8]     = make_float4(p[jj][0], p[jj][1], p[jj][2], p[jj][3]);
                *(float4*)&Es[tx * 2 + jj][ty * 8 + 4] = make_float4(p[jj][4], p[jj][5], p[jj][6], p[jj][7]);
            }
#pragma unroll
            for (int rr = 0; rr < 8; rr++) psum[ty * 8 + rr][tx] += rs[rr];
        }
        __syncthreads();

#pragma unroll 8
        for (int k = 0; k < 32; k++) {
            const u64* ap = (const u64*)&Es[k][ty * 8];
            u64 a0 = ap[0], a1 = ap[1], a2 = ap[2], a3 = ap[3];
            float4 bv = *(const float4*)&Vs[k][tx * 4];
            u64 b0 = pack2(bv.x, bv.x), b1 = pack2(bv.y, bv.y);
            u64 b2 = pack2(bv.z, bv.z), b3 = pack2(bv.w, bv.w);
            o2[0][0] = fma2(a0, b0, o2[0][0]); o2[0][1] = fma2(a0, b1, o2[0][1]);
            o2[0][2] = fma2(a0, b2, o2[0][2]); o2[0][3] = fma2(a0, b3, o2[0][3]);
            o2[1][0] = fma2(a1, b0, o2[1][0]); o2[1][1] = fma2(a1, b1, o2[1][1]);
            o2[1][2] = fma2(a1, b2, o2[1][2]); o2[1][3] = fma2(a1, b3, o2[1][3]);
            o2[2][0] = fma2(a2, b0, o2[2][0]); o2[2][1] = fma2(a2, b1, o2[2][1]);
            o2[2][2] = fma2(a2, b2, o2[2][2]); o2[2][3] = fma2(a2, b3, o2[2][3]);
            o2[3][0] = fma2(a3, b0, o2[3][0]); o2[3][1] = fma2(a3, b1, o2[3][1]);
            o2[3][2] = fma2(a3, b2, o2[3][2]); o2[3][3] = fma2(a3, b3, o2[3][3]);
        }
        __syncthreads();
    }

    if (tid < 128) {
        float s = 0.0f;
#pragma unroll
        for (int x = 0; x < 16; x++) s += psum[tid][x];
        rsum[tid] = s;
    }
    __syncthreads();

#pragma unroll
    for (int mi = 0; mi < 4; mi++) {
        int m = ty * 8 + 2 * mi;
        float inv0 = 1.0f / rsum[m], inv1 = 1.0f / rsum[m + 1];
        float r0[4], r1[4];
#pragma unroll
        for (int d = 0; d < 4; d++) {
            float lo, hi;
            unpack2(o2[mi][d], lo, hi);
            r0[d] = lo * inv0; r1[d] = hi * inv1;
        }
        float* outp = g_attno + ((size_t)(b * T_) + i0 + m) * D_ + h * HD_ + tx * 4;
        *(float4*)outp        = make_float4(r0[0], r0[1], r0[2], r0[3]);
        *(float4*)(outp + D_) = make_float4(r1[0], r1[1], r1[2], r1[3]);
    }
}

// ---------------------------------------------------------------------------
// Launch
// ---------------------------------------------------------------------------
extern "C" void kernel_launch(void* const* d_in, const int* in_sizes, int n_in,
                              void* d_out, int out_size) {
    const float* x     = (const float*)d_in[0];
    const float* sc    = (const float*)d_in[1];
    const float* sd    = (const float*)d_in[2];
    const float* ls    = (const float*)d_in[3];
    const float* la    = (const float*)d_in[4];
    const float* ms    = (const float*)d_in[5];
    const float* temp  = (const float*)d_in[6];
    const float* qkv_w = (const float*)d_in[7];
    const float* out_w = (const float*)d_in[8];
    float* out = (float*)d_out;

    cudaFuncSetAttribute(qkv_gemm_tc, cudaFuncAttributeMaxDynamicSharedMemorySize, TCG_SMEM);
    cudaFuncSetAttribute(out_gemm_tc, cudaFuncAttributeMaxDynamicSharedMemorySize, TCG_SMEM);

    params_kernel<<<1, 256>>>(sc, sd, ls, la, ms, temp);
    qkv_gemm_tc<<<dim3(N3D_ / 128, BT_ / 128), 256, TCG_SMEM>>>(x, qkv_w);
    splat_weights_kernel<<<dim3(T_ / 16, B_ * H_), 256>>>();
    flash_kernel<<<dim3(T_ / 128, B_ * H_), 256>>>();
    out_gemm_tc<<<dim3(D_ / 128, BT_ / 128), 256, TCG_SMEM>>>(out_w, out);
}

// round 7
// speedup vs baseline: 1.4797x; 1.0502x over previous
#include <cuda_runtime.h>
#include <cuda_bf16.h>

// Problem constants
#define B_   2
#define T_   2048
#define D_   1024
#define H_   16
#define S_   16
#define HD_  64
#define BT_  (B_ * T_)     // 4096
#define N3D_ (3 * D_)      // 3072

// ---------------------------------------------------------------------------
// Workspaces (device globals — no allocation allowed)
// ---------------------------------------------------------------------------
__device__ float g_qkv[BT_ * N3D_];          // (b,t,{q,k,v},h,hd)
__device__ float g_attno[BT_ * D_];          // attention output (b,t,h,hd)
__device__ float g_qwa[B_ * H_ * T_ * S_];   // q splat weights * amplitude
__device__ float g_kw [B_ * H_ * T_ * S_];   // k splat weights
__device__ float g_centers[H_ * S_ * HD_];
__device__ float g_invvar[H_ * S_];
__device__ float g_amp[H_ * S_];
__device__ float g_shift[H_];
__device__ float g_invtemp;

typedef unsigned long long u64;

// ---------------------------------------------------------------------------
// f32x2 helpers
// ---------------------------------------------------------------------------
__device__ __forceinline__ u64 pack2(float lo, float hi) {
    u64 r; asm("mov.b64 %0, {%1, %2};" : "=l"(r) : "f"(lo), "f"(hi)); return r;
}
__device__ __forceinline__ u64 fma2(u64 a, u64 b, u64 c) {
    u64 d; asm("fma.rn.f32x2 %0, %1, %2, %3;" : "=l"(d) : "l"(a), "l"(b), "l"(c)); return d;
}
__device__ __forceinline__ void unpack2(u64 v, float& lo, float& hi) {
    asm("mov.b64 {%0, %1}, %2;" : "=f"(lo), "=f"(hi) : "l"(v));
}

// ---------------------------------------------------------------------------
// mma.sync helpers (sm_80+ path)
// ---------------------------------------------------------------------------
__device__ __forceinline__ unsigned smem_u32(const void* p) {
    unsigned a;
    asm("{ .reg .u64 t; cvta.to.shared.u64 t, %1; cvt.u32.u64 %0, t; }" : "=r"(a) : "l"(p));
    return a;
}
__device__ __forceinline__ void ldsm_x4(unsigned* r, unsigned addr) {
    asm volatile("ldmatrix.sync.aligned.m8n8.x4.shared.b16 {%0,%1,%2,%3}, [%4];"
                 : "=r"(r[0]), "=r"(r[1]), "=r"(r[2]), "=r"(r[3]) : "r"(addr));
}
__device__ __forceinline__ void ldsm_x4t(unsigned* r, unsigned addr) {
    asm volatile("ldmatrix.sync.aligned.m8n8.x4.trans.shared.b16 {%0,%1,%2,%3}, [%4];"
                 : "=r"(r[0]), "=r"(r[1]), "=r"(r[2]), "=r"(r[3]) : "r"(addr));
}
__device__ __forceinline__ void ldsm_x2(unsigned* r, unsigned addr) {
    asm volatile("ldmatrix.sync.aligned.m8n8.x2.shared.b16 {%0,%1}, [%2];"
                 : "=r"(r[0]), "=r"(r[1]) : "r"(addr));
}
__device__ __forceinline__ void mma_bf16(float* c, const unsigned* a, const unsigned* b) {
    asm volatile("mma.sync.aligned.m16n8k16.row.col.f32.bf16.bf16.f32 "
                 "{%0,%1,%2,%3}, {%4,%5,%6,%7}, {%8,%9}, {%0,%1,%2,%3};"
                 : "+f"(c[0]), "+f"(c[1]), "+f"(c[2]), "+f"(c[3])
                 : "r"(a[0]), "r"(a[1]), "r"(a[2]), "r"(a[3]), "r"(b[0]), "r"(b[1]));
}
__device__ __forceinline__ unsigned swz(unsigned off) {        // 64B-row GEMM swizzle
    return off ^ (((off >> 7) & 3u) << 4);
}
__device__ __forceinline__ unsigned swz128(unsigned off) {     // 128B-row swizzle
    return off ^ ((off >> 3) & 0x70u);
}

// ---------------------------------------------------------------------------
// Kernel 1: splat parameters (tiny)
// ---------------------------------------------------------------------------
__global__ void params_kernel(const float* __restrict__ sc, const float* __restrict__ sd,
                              const float* __restrict__ ls, const float* __restrict__ la,
                              const float* __restrict__ ms, const float* __restrict__ temp) {
    const int tid = threadIdx.x;
    const float sig = 1.0f / (1.0f + expf(-ms[0]));
    const float mv = sig * 0.2f;
    for (int i = tid; i < H_ * S_ * HD_; i += 256)
        g_centers[i] = sc[i] + sd[i] * mv;
    {
        float scale = fminf(fmaxf(expf(ls[tid]), 0.01f), 2.0f);
        g_invvar[tid] = -0.5f / (scale * scale + 1e-8f);
        g_amp[tid] = fminf(fmaxf(expf(la[tid]), 1e-6f), 10.0f);
    }
    __syncthreads();
    if (tid < H_) {
        float t = fminf(fmaxf(temp[0], 0.1f), 10.0f);
        float it = 1.0f / t;
        float ssum = 0.0f;
        for (int s = 0; s < S_; s++) ssum += g_amp[tid * S_ + s];
        g_shift[tid] = 0.5f * ssum * it;
        if (tid == 0) g_invtemp = it;
    }
}

// ---------------------------------------------------------------------------
// Split-bf16 tensor-core NT GEMM (R5-proven)
// ---------------------------------------------------------------------------
#define TCG_STAGE 32768
#define TCG_SMEM  (2 * TCG_STAGE)

__device__ __forceinline__ void cvt_store16(const float* v, char* hi_b, char* lo_b, int r, int h) {
#pragma unroll
    for (int i = 0; i < 8; i++) {
        float x0 = v[2 * i], x1 = v[2 * i + 1];
        __nv_bfloat16 h0 = __float2bfloat16(x0), h1 = __float2bfloat16(x1);
        __nv_bfloat16 l0 = __float2bfloat16(x0 - __bfloat162float(h0));
        __nv_bfloat16 l1 = __float2bfloat16(x1 - __bfloat162float(h1));
        unsigned off = swz((unsigned)(r * 64 + h * 32 + i * 4));
        *(__nv_bfloat162*)(hi_b + off) = __nv_bfloat162(h0, h1);
        *(__nv_bfloat162*)(lo_b + off) = __nv_bfloat162(l0, l1);
    }
}

__device__ __forceinline__ void tc_load_chunk(
    const float* __restrict__ A, const float* __restrict__ Bw, int K,
    char* stage, int c, int m0, int n0, int tid)
{
    const int r = tid >> 1, h = tid & 1;
    const float* ap = A + (size_t)(m0 + r) * K + c * 32 + h * 16;
    const float* bp = Bw + (size_t)(n0 + r) * K + c * 32 + h * 16;
    float va[16], vb[16];
#pragma unroll
    for (int i = 0; i < 4; i++) *(float4*)&va[i * 4] = *(const float4*)(ap + i * 4);
#pragma unroll
    for (int i = 0; i < 4; i++) *(float4*)&vb[i * 4] = *(const float4*)(bp + i * 4);
    cvt_store16(va, stage,          stage + 8192,  r, h);
    cvt_store16(vb, stage + 16384,  stage + 24576, r, h);
}

__device__ __forceinline__ void tc_gemm_nt_body(
    const float* __restrict__ A, const float* __restrict__ Bw,
    float* __restrict__ C, int N, int K)
{
    extern __shared__ char gs[];
    const int tid = threadIdx.x;
    const int m0 = blockIdx.y * 128, n0 = blockIdx.x * 128;
    const int NC = K / 32;
    const unsigned sbase = smem_u32(gs);

    const int warp = tid >> 5, lane = tid & 31;
    const int wm = warp >> 2, wn = warp & 3;
    const int a_row = lane & 15;
    const int a_kb  = (lane >> 4) * 16;
    const int b_row = lane & 7;
    const int b_kb  = ((lane >> 3) & 1) * 16;

    float acc[4][4][4];
#pragma unroll
    for (int i = 0; i < 4; i++)
#pragma unroll
        for (int j = 0; j < 4; j++)
#pragma unroll
            for (int q = 0; q < 4; q++) acc[i][j][q] = 0.0f;

    tc_load_chunk(A, Bw, K, gs, 0, m0, n0, tid);

    for (int c = 0; c < NC; c++) {
        const int s = c & 1;
        __syncthreads();
        const unsigned stA_hi = sbase + s * TCG_STAGE;
        const unsigned stA_lo = stA_hi + 8192;
        const unsigned stB_hi = stA_hi + 16384;
        const unsigned stB_lo = stA_hi + 24576;

#pragma unroll
        for (int kh = 0; kh < 2; kh++) {
            unsigned a[4][4], bh[4][2], bl[4][2];
#pragma unroll
            for (int mt = 0; mt < 4; mt++) {
                unsigned off = (unsigned)((wm * 64 + mt * 16 + a_row) * 64 + kh * 32 + a_kb);
                ldsm_x4(a[mt], stA_hi + swz(off));
            }
#pragma unroll
            for (int nt = 0; nt < 4; nt++) {
                unsigned off = (unsigned)((wn * 32 + nt * 8 + b_row) * 64 + kh * 32 + b_kb);
                ldsm_x2(bh[nt], stB_hi + swz(off));
                ldsm_x2(bl[nt], stB_lo + swz(off));
            }
#pragma unroll
            for (int mt = 0; mt < 4; mt++)
#pragma unroll
                for (int nt = 0; nt < 4; nt++) mma_bf16(acc[mt][nt], a[mt], bh[nt]);
#pragma unroll
            for (int mt = 0; mt < 4; mt++)
#pragma unroll
                for (int nt = 0; nt < 4; nt++) mma_bf16(acc[mt][nt], a[mt], bl[nt]);
#pragma unroll
            for (int mt = 0; mt < 4; mt++) {
                unsigned off = (unsigned)((wm * 64 + mt * 16 + a_row) * 64 + kh * 32 + a_kb);
                ldsm_x4(a[mt], stA_lo + swz(off));
            }
#pragma unroll
            for (int mt = 0; mt < 4; mt++)
#pragma unroll
                for (int nt = 0; nt < 4; nt++) mma_bf16(acc[mt][nt], a[mt], bh[nt]);
        }

        if (c + 1 < NC)
            tc_load_chunk(A, Bw, K, gs + (s ^ 1) * TCG_STAGE, c + 1, m0, n0, tid);
    }

    const int qrow = lane >> 2, qcol = (lane & 3) * 2;
#pragma unroll
    for (int mt = 0; mt < 4; mt++) {
#pragma unroll
        for (int nt = 0; nt < 4; nt++) {
            int m = m0 + wm * 64 + mt * 16 + qrow;
            int n = n0 + wn * 32 + nt * 8 + qcol;
            *(float2*)&C[(size_t)m * N + n]       = make_float2(acc[mt][nt][0], acc[mt][nt][1]);
            *(float2*)&C[(size_t)(m + 8) * N + n] = make_float2(acc[mt][nt][2], acc[mt][nt][3]);
        }
    }
}

__global__ __launch_bounds__(256, 2)
void qkv_gemm_tc(const float* __restrict__ x, const float* __restrict__ qkv_w) {
    tc_gemm_nt_body(x, qkv_w, g_qkv, N3D_, D_);
}
__global__ __launch_bounds__(256, 2)
void out_gemm_tc(const float* __restrict__ out_w, float* __restrict__ out) {
    tc_gemm_nt_body(g_attno, out_w, out, D_, D_);
}

// ---------------------------------------------------------------------------
// Kernel 3: splat weights (unchanged)
// ---------------------------------------------------------------------------
__global__ __launch_bounds__(256) void splat_weights_kernel() {
    __shared__ float qsm[16][65], ksm2[16][65], csm[16][65];
    __shared__ float ivv[16], amps[16];
    const int tid = threadIdx.x;
    const int bh = blockIdx.y, b = bh >> 4, h = bh & 15;
    const int t0 = blockIdx.x * 16;

    for (int idx = tid; idx < 16 * 64; idx += 256) {
        int s = idx >> 6, d = idx & 63;
        csm[s][d] = g_centers[(h * 16 + s) * 64 + d];
    }
    if (tid < 16) { ivv[tid] = g_invvar[h * 16 + tid]; amps[tid] = g_amp[h * 16 + tid]; }
    for (int idx = tid; idx < 16 * 64; idx += 256) {
        int tt = idx >> 6, d = idx & 63;
        size_t base = ((size_t)(b * T_ + t0 + tt) * 3) * D_ + h * 64 + d;
        qsm[tt][d] = g_qkv[base];
        ksm2[tt][d] = g_qkv[base + D_];
    }
    __syncthreads();

    const int s = tid & 15, tt = tid >> 4;
    float dq = 0.0f, dk = 0.0f;
#pragma unroll
    for (int d = 0; d < 64; d++) {
        float c = csm[s][d];
        float x1 = qsm[tt][d] - c; dq = fmaf(x1, x1, dq);
        float x2 = ksm2[tt][d] - c; dk = fmaf(x2, x2, dk);
    }
    size_t oidx = ((size_t)bh * T_ + t0 + tt) * S_ + s;
    g_qwa[oidx] = __expf(dq * ivv[s]) * amps[s];
    g_kw[oidx]  = __expf(dk * ivv[s]);
}

// ---------------------------------------------------------------------------
// Kernel 4: flash v3 — stage 1 FFMA2 fp32 (exact logits+exp), stage 2 split-bf16
// tensor cores. j-tile 64. E stored to smem as bf16 hi/lo (128B rows, SW128),
// V tile converted to bf16 hi/lo (j,d), B-read via ldmatrix.trans.
// Warp grid 4(m)x2(n), warp tile 32x32, 32 fp32 acc held across loop.
// ---------------------------------------------------------------------------
#define FL_QS   0
#define FL_KSH  8192
#define FL_EH   12288
#define FL_EL   28672
#define FL_VH   45056
#define FL_VL   53248
#define FL_PSU  61440
#define FL_RSU  70144
#define FL_SMEM 70656

__global__ __launch_bounds__(256, 2) void flash_kernel() {
    extern __shared__ char fsm[];
    float* qs   = (float*)(fsm + FL_QS);     // [s][128]
    float* ksh  = (float*)(fsm + FL_KSH);    // [s][64]
    char*  Ehb  = fsm + FL_EH;
    char*  Elb  = fsm + FL_EL;
    char*  Vhb  = fsm + FL_VH;
    char*  Vlb  = fsm + FL_VL;
    float* psum = (float*)(fsm + FL_PSU);    // [128][17]
    float* rsum = (float*)(fsm + FL_RSU);
    const unsigned sb = smem_u32(fsm);

    const int tid = threadIdx.x;
    const int bh = blockIdx.y, b = bh >> 4, h = bh & 15;
    const int i0 = blockIdx.x * 128;
    const float* qwa = g_qwa + ((size_t)bh * T_ + i0) * S_;
    const float* kwp = g_kw + (size_t)bh * T_ * S_;
    const float* vp  = g_qkv + ((size_t)b * T_ * 3 + 2) * D_ + h * HD_;  // row stride 3072
    const float invtemp = g_invtemp;
    const float shift = g_shift[h];

    // stage-1 ownership
    const int tx = tid & 15, ty = tid >> 4;
    // stage-2 ownership
    const int warp = tid >> 5, lane = tid & 31;
    const int wm = warp >> 1, wn = warp & 1;
    const int arow = lane & 15, akb = (lane >> 4) * 16;
    const int brow = lane & 15, bcb = (lane >> 4) * 8;

    // load qwa tile transposed [s][m]
    for (int f = tid; f < 512; f += 256) {
        int r = f >> 2, c4 = (f & 3) << 2;
        float4 v = *(const float4*)(qwa + r * 16 + c4);
        qs[(c4 + 0) * 128 + r] = v.x; qs[(c4 + 1) * 128 + r] = v.y;
        qs[(c4 + 2) * 128 + r] = v.z; qs[(c4 + 3) * 128 + r] = v.w;
    }
    for (int f = tid; f < 128 * 17; f += 256) psum[f] = 0.0f;

    float acc[2][4][4];
#pragma unroll
    for (int i = 0; i < 2; i++)
#pragma unroll
        for (int j = 0; j < 4; j++)
#pragma unroll
            for (int q = 0; q < 4; q++) acc[i][j][q] = 0.0f;

    for (int j0 = 0; j0 < T_; j0 += 64) {
        // kw tile 64x16 -> ksh[s][j]
        {
            int r = tid >> 2, c4 = (tid & 3) << 2;
            float4 v = *(const float4*)(kwp + (size_t)(j0 + r) * 16 + c4);
            ksh[(c4 + 0) * 64 + r] = v.x; ksh[(c4 + 1) * 64 + r] = v.y;
            ksh[(c4 + 2) * 64 + r] = v.z; ksh[(c4 + 3) * 64 + r] = v.w;
        }
        // V tile 64x64 fp32 -> bf16 hi/lo smem (j,d), 128B rows, SW128
        {
            int r = tid >> 2, c0 = (tid & 3) * 16;
            float vv[16];
#pragma unroll
            for (int i = 0; i < 4; i++)
                *(float4*)&vv[i * 4] = *(const float4*)(vp + (size_t)(j0 + r) * 3072 + c0 + i * 4);
#pragma unroll
            for (int i = 0; i < 8; i++) {
                float x0 = vv[2 * i], x1 = vv[2 * i + 1];
                __nv_bfloat16 h0 = __float2bfloat16(x0), h1 = __float2bfloat16(x1);
                __nv_bfloat16 l0 = __float2bfloat16(x0 - __bfloat162float(h0));
                __nv_bfloat16 l1 = __float2bfloat16(x1 - __bfloat162float(h1));
                unsigned off = swz128((unsigned)(r * 128 + (c0 + 2 * i) * 2));
                *(__nv_bfloat162*)(Vhb + off) = __nv_bfloat162(h0, h1);
                *(__nv_bfloat162*)(Vlb + off) = __nv_bfloat162(l0, l1);
            }
        }
        __syncthreads();

        // ---- stage 1: logits 8m x 2j per half, exp, store split-bf16 E
        {
            float rs[8];
#pragma unroll
            for (int rr = 0; rr < 8; rr++) rs[rr] = 0.0f;
#pragma unroll
            for (int hf = 0; hf < 2; hf++) {
                u64 l2[2][4];
#pragma unroll
                for (int jj = 0; jj < 2; jj++)
#pragma unroll
                    for (int mi = 0; mi < 4; mi++) l2[jj][mi] = 0ull;
#pragma unroll
                for (int s = 0; s < 16; s++) {
                    const u64* ap = (const u64*)&qs[s * 128 + ty * 8];
                    u64 a0 = ap[0], a1 = ap[1], a2 = ap[2], a3 = ap[3];
                    float bk0 = ksh[s * 64 + hf * 32 + tx * 2];
                    float bk1 = ksh[s * 64 + hf * 32 + tx * 2 + 1];
                    u64 b0 = pack2(bk0, bk0), b1 = pack2(bk1, bk1);
                    l2[0][0] = fma2(a0, b0, l2[0][0]); l2[0][1] = fma2(a1, b0, l2[0][1]);
                    l2[0][2] = fma2(a2, b0, l2[0][2]); l2[0][3] = fma2(a3, b0, l2[0][3]);
                    l2[1][0] = fma2(a0, b1, l2[1][0]); l2[1][1] = fma2(a1, b1, l2[1][1]);
                    l2[1][2] = fma2(a2, b1, l2[1][2]); l2[1][3] = fma2(a3, b1, l2[1][3]);
                }
#pragma unroll
                for (int mi = 0; mi < 4; mi++) {
                    float e00, e01, e10, e11;
                    unpack2(l2[0][mi], e00, e01);   // j = tx*2,   rows 2mi, 2mi+1
                    unpack2(l2[1][mi], e10, e11);   // j = tx*2+1
                    e00 = __expf(fmaf(e00, invtemp, -shift));
                    e01 = __expf(fmaf(e01, invtemp, -shift));
                    e10 = __expf(fmaf(e10, invtemp, -shift));
                    e11 = __expf(fmaf(e11, invtemp, -shift));
                    rs[2 * mi]     += e00 + e10;
                    rs[2 * mi + 1] += e01 + e11;
                    // row r0 = ty*8 + 2mi : pair (e00, e10); row r1: (e01, e11)
                    int r0 = ty * 8 + 2 * mi;
                    unsigned off0 = swz128((unsigned)(r0 * 128 + hf * 64 + tx * 4));
                    unsigned off1 = swz128((unsigned)((r0 + 1) * 128 + hf * 64 + tx * 4));
                    __nv_bfloat16 h00 = __float2bfloat16(e00), h10 = __float2bfloat16(e10);
                    __nv_bfloat16 h01 = __float2bfloat16(e01), h11 = __float2bfloat16(e11);
                    __nv_bfloat16 l00 = __float2bfloat16(e00 - __bfloat162float(h00));
                    __nv_bfloat16 l10 = __float2bfloat16(e10 - __bfloat162float(h10));
                    __nv_bfloat16 l01 = __float2bfloat16(e01 - __bfloat162float(h01));
                    __nv_bfloat16 l11 = __float2bfloat16(e11 - __bfloat162float(h11));
                    *(__nv_bfloat162*)(Ehb + off0) = __nv_bfloat162(h00, h10);
                    *(__nv_bfloat162*)(Elb + off0) = __nv_bfloat162(l00, l10);
                    *(__nv_bfloat162*)(Ehb + off1) = __nv_bfloat162(h01, h11);
                    *(__nv_bfloat162*)(Elb + off1) = __nv_bfloat162(l01, l11);
                }
            }
#pragma unroll
            for (int rr = 0; rr < 8; rr++) psum[(ty * 8 + rr) * 17 + tx] += rs[rr];
        }
        __syncthreads();

        // ---- stage 2: O += E * V via split-bf16 mma (hh + hl + lh)
#pragma unroll
        for (int kc = 0; kc < 4; kc++) {
            unsigned a[2][4], bh2[2][4], bl2[2][4];
#pragma unroll
            for (int mt = 0; mt < 2; mt++) {
                unsigned off = swz128((unsigned)((wm * 32 + mt * 16 + arow) * 128 + kc * 32 + akb));
                ldsm_x4(a[mt], sb + FL_EH + off);
            }
#pragma unroll
            for (int nh = 0; nh < 2; nh++) {
                unsigned off = swz128((unsigned)((kc * 16 + brow) * 128 + (wn * 32 + nh * 16 + bcb) * 2));
                ldsm_x4t(bh2[nh], sb + FL_VH + off);
                ldsm_x4t(bl2[nh], sb + FL_VL + off);
            }
            // hh
#pragma unroll
            for (int mt = 0; mt < 2; mt++)
#pragma unroll
                for (int nh = 0; nh < 2; nh++) {
                    mma_bf16(acc[mt][nh * 2],     a[mt], &bh2[nh][0]);
                    mma_bf16(acc[mt][nh * 2 + 1], a[mt], &bh2[nh][2]);
                }
            // hl
#pragma unroll
            for (int mt = 0; mt < 2; mt++)
#pragma unroll
                for (int nh = 0; nh < 2; nh++) {
                    mma_bf16(acc[mt][nh * 2],     a[mt], &bl2[nh][0]);
                    mma_bf16(acc[mt][nh * 2 + 1], a[mt], &bl2[nh][2]);
                }
            // lh
#pragma unroll
            for (int mt = 0; mt < 2; mt++) {
                unsigned off = swz128((unsigned)((wm * 32 + mt * 16 + arow) * 128 + kc * 32 + akb));
                ldsm_x4(a[mt], sb + FL_EL + off);
            }
#pragma unroll
            for (int mt = 0; mt < 2; mt++)
#pragma unroll
                for (int nh = 0; nh < 2; nh++) {
                    mma_bf16(acc[mt][nh * 2],     a[mt], &bh2[nh][0]);
                    mma_bf16(acc[mt][nh * 2 + 1], a[mt], &bh2[nh][2]);
                }
        }
        __syncthreads();
    }

    if (tid < 128) {
        float s = 0.0f;
#pragma unroll
        for (int x = 0; x < 16; x++) s += psum[tid * 17 + x];
        rsum[tid] = s;
    }
    __syncthreads();

    // epilogue
    const int qrow = lane >> 2, qcol = (lane & 3) * 2;
#pragma unroll
    for (int mt = 0; mt < 2; mt++) {
        int m_lo = wm * 32 + mt * 16 + qrow;
        float inv0 = 1.0f / rsum[m_lo];
        float inv1 = 1.0f / rsum[m_lo + 8];
#pragma unroll
        for (int nt = 0; nt < 4; nt++) {
            int n = wn * 32 + nt * 8 + qcol;
            float* o0 = g_attno + ((size_t)(b * T_) + i0 + m_lo) * D_ + h * HD_ + n;
            float* o1 = g_attno + ((size_t)(b * T_) + i0 + m_lo + 8) * D_ + h * HD_ + n;
            *(float2*)o0 = make_float2(acc[mt][nt][0] * inv0, acc[mt][nt][1] * inv0);
            *(float2*)o1 = make_float2(acc[mt][nt][2] * inv1, acc[mt][nt][3] * inv1);
        }
    }
}

// ---------------------------------------------------------------------------
// Launch
// ---------------------------------------------------------------------------
extern "C" void kernel_launch(void* const* d_in, const int* in_sizes, int n_in,
                              void* d_out, int out_size) {
    const float* x     = (const float*)d_in[0];
    const float* sc    = (const float*)d_in[1];
    const float* sd    = (const float*)d_in[2];
    const float* ls    = (const float*)d_in[3];
    const float* la    = (const float*)d_in[4];
    const float* ms    = (const float*)d_in[5];
    const float* temp  = (const float*)d_in[6];
    const float* qkv_w = (const float*)d_in[7];
    const float* out_w = (const float*)d_in[8];
    float* out = (float*)d_out;

    cudaFuncSetAttribute(qkv_gemm_tc, cudaFuncAttributeMaxDynamicSharedMemorySize, TCG_SMEM);
    cudaFuncSetAttribute(out_gemm_tc, cudaFuncAttributeMaxDynamicSharedMemorySize, TCG_SMEM);
    cudaFuncSetAttribute(flash_kernel, cudaFuncAttributeMaxDynamicSharedMemorySize, FL_SMEM);

    params_kernel<<<1, 256>>>(sc, sd, ls, la, ms, temp);
    qkv_gemm_tc<<<dim3(N3D_ / 128, BT_ / 128), 256, TCG_SMEM>>>(x, qkv_w);
    splat_weights_kernel<<<dim3(T_ / 16, B_ * H_), 256>>>();
    flash_kernel<<<dim3(T_ / 128, B_ * H_), 256, FL_SMEM>>>();
    out_gemm_tc<<<dim3(D_ / 128, BT_ / 128), 256, TCG_SMEM>>>(out_w, out);
}